// round 9
// baseline (speedup 1.0000x reference)
#include <cuda_runtime.h>
#include <cuda_bf16.h>
#include <cstdint>
#include <math.h>

// Problem dims (fixed per reference setup_inputs)
#define NB 64
#define NT 512
#define ND 512
#define NH 1024
#define NG 4096
#define NM (NB * NT)
#define NCTA 128     // persistent grid: 128 CTAs (one per 8-column slice of H)

// ---------------------------------------------------------------------------
// Device scratch (allocation-free rule: __device__ globals)
// xW and h buffers are TIME-MAJOR: xW[t][b][4H], h[t][b][H].
// ---------------------------------------------------------------------------
__device__ float g_xW[(size_t)NM * NG];
__device__ __nv_bfloat16 g_xh[(size_t)NM * ND], g_xl[(size_t)NM * ND];   // x in [T][B][D]
__device__ __nv_bfloat16 g_hh[(size_t)NM * NH], g_hl[(size_t)NM * NH];   // h in [T][B][H]
// Pre-split, transposed weights: [N=4096][K] bf16 hi/lo
__device__ __nv_bfloat16 g_Wx0h[(size_t)NG * ND], g_Wx0l[(size_t)NG * ND];
__device__ __nv_bfloat16 g_Wh0h[(size_t)NG * NH], g_Wh0l[(size_t)NG * NH];
__device__ __nv_bfloat16 g_Wx1h[(size_t)NG * NH], g_Wx1l[(size_t)NG * NH];
__device__ __nv_bfloat16 g_Wh1h[(size_t)NG * NH], g_Wh1l[(size_t)NG * NH];
// Grid barrier state (zero-initialized; proven in rounds 2/6/8)
__device__ unsigned g_barcnt = 0;
__device__ volatile unsigned g_bargen = 0;
__device__ float g_dummy;

// ---------------------------------------------------------------------------
// Helpers (NO tcgen05 — ptxas target is sm_100 plain)
// ---------------------------------------------------------------------------
__device__ __forceinline__ void cp16(uint32_t dst, const void* src) {
    asm volatile("cp.async.cg.shared.global [%0], [%1], 16;" :: "r"(dst), "l"(src));
}
__device__ __forceinline__ void cp_commit() {
    asm volatile("cp.async.commit_group;");
}
template <int N> __device__ __forceinline__ void cp_wait() {
    asm volatile("cp.async.wait_group %0;" :: "n"(N));
}

__device__ __forceinline__ void mma_bf16(float c[4], const uint32_t a[4],
                                         const uint32_t b[2]) {
    asm volatile(
        "mma.sync.aligned.m16n8k16.row.col.f32.bf16.bf16.f32 "
        "{%0,%1,%2,%3}, {%4,%5,%6,%7}, {%8,%9}, {%0,%1,%2,%3};"
        : "+f"(c[0]), "+f"(c[1]), "+f"(c[2]), "+f"(c[3])
        : "r"(a[0]), "r"(a[1]), "r"(a[2]), "r"(a[3]), "r"(b[0]), "r"(b[1]));
}

// Grid barrier — round-6 implementation (passed on hardware 3x). Bounded spin.
__device__ __forceinline__ void grid_sync() {
    __threadfence();
    __syncthreads();
    if (threadIdx.x == 0) {
        unsigned gen = g_bargen;
        if (atomicAdd(&g_barcnt, 1u) == NCTA - 1) {
            g_barcnt = 0;
            __threadfence();
            g_bargen = gen + 1;
        } else {
            for (long i = 0; i < 200000000L && g_bargen == gen; i++) { }
        }
    }
    __syncthreads();
    __threadfence();
}

// Tiny no-op node: shifts lstm_seq L0 to replay index 3 (the ncu capture slot).
__global__ void nudge() {
    if (threadIdx.x == 0) g_dummy = 1.0f;
}

// ---------------------------------------------------------------------------
// Fused split kernel. Region 0 also PERMUTES x from [B][T][D] to [T][B][D].
// ---------------------------------------------------------------------------
__global__ void split_all(
    const float* __restrict__ x,   const float* __restrict__ Wx0,
    const float* __restrict__ Wh0, const float* __restrict__ Wx1,
    const float* __restrict__ Wh1,
    __nv_bfloat16* __restrict__ xh,   __nv_bfloat16* __restrict__ xl,
    __nv_bfloat16* __restrict__ wx0h, __nv_bfloat16* __restrict__ wx0l,
    __nv_bfloat16* __restrict__ wh0h, __nv_bfloat16* __restrict__ wh0l,
    __nv_bfloat16* __restrict__ wx1h, __nv_bfloat16* __restrict__ wx1l,
    __nv_bfloat16* __restrict__ wh1h, __nv_bfloat16* __restrict__ wh1l) {
    const long R0 = (long)NM * ND;               // x
    const long R1 = R0 + (long)NG * ND;          // Wx0 (K=ND)
    const long R2 = R1 + (long)NG * NH;          // Wh0 (K=NH)
    const long R3 = R2 + (long)NG * NH;          // Wx1 (K=NH)
    long idx = (long)blockIdx.x * blockDim.x + threadIdx.x;

    float v;
    __nv_bfloat16 *hi, *lo;
    long o;
    if (idx < R0) {
        long b = idx / ((long)NT * ND);
        long rem = idx - b * ((long)NT * ND);
        long t = rem / ND, d = rem - t * ND;
        v = x[idx];
        o = (t * NB + b) * ND + d;               // time-major
        hi = xh; lo = xl;
    } else if (idx < R1) {
        o = idx - R0; long n = o / ND, k = o - n * ND;
        v = Wx0[k * NG + n]; hi = wx0h; lo = wx0l;
    } else if (idx < R2) {
        o = idx - R1; long n = o / NH, k = o - n * NH;
        v = Wh0[k * NG + n]; hi = wh0h; lo = wh0l;
    } else if (idx < R3) {
        o = idx - R2; long n = o / NH, k = o - n * NH;
        v = Wx1[k * NG + n]; hi = wx1h; lo = wx1l;
    } else {
        o = idx - R3; long n = o / NH, k = o - n * NH;
        v = Wh1[k * NG + n]; hi = wh1h; lo = wh1l;
    }
    __nv_bfloat16 h = __float2bfloat16(v);
    hi[o] = h;
    lo[o] = __float2bfloat16(v - __bfloat162float(h));
}
#define SPLIT_TOTAL ((long)NM * ND + (long)NG * ND + 3L * NG * NH)

// ---------------------------------------------------------------------------
// Input-projection GEMM (mma.sync, proven). Row order of A/C is whatever the
// caller uses (here: time-major m = t*NB+b); kernel is order-agnostic.
// ---------------------------------------------------------------------------
__global__ __launch_bounds__(256) void gemm_in(
    const __nv_bfloat16* __restrict__ Ah, const __nv_bfloat16* __restrict__ Al,
    const __nv_bfloat16* __restrict__ Bh, const __nv_bfloat16* __restrict__ Bl,
    const float* __restrict__ bias, float* __restrict__ C, int K) {
    constexpr int BM = 128, BN = 64, BK = 32, AS = BK + 8;
    __shared__ __align__(16) __nv_bfloat16 sAh[BM * AS], sAl[BM * AS];
    __shared__ __align__(16) __nv_bfloat16 sBh[BN * AS], sBl[BN * AS];

    const int tid = threadIdx.x, lane = tid & 31, wid = tid >> 5;
    const int g = lane >> 2, tg = lane & 3;
    const int wm = wid & 3, wn = wid >> 2;
    const int m0 = blockIdx.y * BM, n0 = blockIdx.x * BN;

    float acc[2][4][4];
#pragma unroll
    for (int mt = 0; mt < 2; mt++)
#pragma unroll
        for (int nt = 0; nt < 4; nt++)
#pragma unroll
            for (int q = 0; q < 4; q++) acc[mt][nt][q] = 0.f;

    for (int k0 = 0; k0 < K; k0 += BK) {
#pragma unroll
        for (int i = 0; i < 2; i++) {
            int e = tid + i * 256;
            int r = e >> 2, k8 = (e & 3) << 3;
            *(uint4*)(sAh + r * AS + k8) =
                *(const uint4*)(Ah + (size_t)(m0 + r) * K + k0 + k8);
            *(uint4*)(sAl + r * AS + k8) =
                *(const uint4*)(Al + (size_t)(m0 + r) * K + k0 + k8);
        }
        {
            int r = tid >> 2, k8 = (tid & 3) << 3;
            *(uint4*)(sBh + r * AS + k8) =
                *(const uint4*)(Bh + (size_t)(n0 + r) * K + k0 + k8);
            *(uint4*)(sBl + r * AS + k8) =
                *(const uint4*)(Bl + (size_t)(n0 + r) * K + k0 + k8);
        }
        __syncthreads();

#pragma unroll
        for (int kk = 0; kk < BK; kk += 16) {
            uint32_t ah[2][4], al[2][4], bh[4][2], bl[4][2];
#pragma unroll
            for (int mt = 0; mt < 2; mt++) {
                int rb = wm * 32 + mt * 16;
                ah[mt][0] = *(const uint32_t*)(&sAh[(rb + g) * AS + kk + tg * 2]);
                ah[mt][1] = *(const uint32_t*)(&sAh[(rb + g + 8) * AS + kk + tg * 2]);
                ah[mt][2] = *(const uint32_t*)(&sAh[(rb + g) * AS + kk + tg * 2 + 8]);
                ah[mt][3] = *(const uint32_t*)(&sAh[(rb + g + 8) * AS + kk + tg * 2 + 8]);
                al[mt][0] = *(const uint32_t*)(&sAl[(rb + g) * AS + kk + tg * 2]);
                al[mt][1] = *(const uint32_t*)(&sAl[(rb + g + 8) * AS + kk + tg * 2]);
                al[mt][2] = *(const uint32_t*)(&sAl[(rb + g) * AS + kk + tg * 2 + 8]);
                al[mt][3] = *(const uint32_t*)(&sAl[(rb + g + 8) * AS + kk + tg * 2 + 8]);
            }
#pragma unroll
            for (int nt = 0; nt < 4; nt++) {
                int nb = wn * 32 + nt * 8 + g;
                bh[nt][0] = *(const uint32_t*)(&sBh[nb * AS + kk + tg * 2]);
                bh[nt][1] = *(const uint32_t*)(&sBh[nb * AS + kk + tg * 2 + 8]);
                bl[nt][0] = *(const uint32_t*)(&sBl[nb * AS + kk + tg * 2]);
                bl[nt][1] = *(const uint32_t*)(&sBl[nb * AS + kk + tg * 2 + 8]);
            }
#pragma unroll
            for (int mt = 0; mt < 2; mt++)
#pragma unroll
                for (int nt = 0; nt < 4; nt++) {
                    mma_bf16(acc[mt][nt], ah[mt], bh[nt]);
                    mma_bf16(acc[mt][nt], ah[mt], bl[nt]);
                    mma_bf16(acc[mt][nt], al[mt], bh[nt]);
                }
        }
        __syncthreads();
    }

#pragma unroll
    for (int mt = 0; mt < 2; mt++) {
        int row = m0 + wm * 32 + mt * 16 + g;
#pragma unroll
        for (int nt = 0; nt < 4; nt++) {
            int col = n0 + wn * 32 + nt * 8 + tg * 2;
            float b0v = bias[col], b1v = bias[col + 1];
            C[(size_t)row * NG + col]           = acc[mt][nt][0] + b0v;
            C[(size_t)row * NG + col + 1]       = acc[mt][nt][1] + b1v;
            C[(size_t)(row + 8) * NG + col]     = acc[mt][nt][2] + b0v;
            C[(size_t)(row + 8) * NG + col + 1] = acc[mt][nt][3] + b1v;
        }
    }
}

// ---------------------------------------------------------------------------
// Persistent recurrent kernel — 512 THREADS (16 warps, 4/SMSP for latency
// hiding; was 8 warps = 2/SMSP and latency-bound).
// Warp layout: mh = wid>>2 (16-row M tile), ks = wid&3 (K quarter); each warp
// computes all 32 N cols. Time-major h/xW: h(t) is a contiguous 128KB block.
// ks-partials go to zs4[4][64][32] aliasing the dead A buffers.
// ---------------------------------------------------------------------------
#define SEQ_SMEM (2 * 32 * 1032 * 2 + 2 * 2 * 64 * 136 * 2 + 64 * 32 * 4)  // 209920

__global__ __launch_bounds__(512) void lstm_seq(
    const float* __restrict__ xW,                 // [T][B][4H]
    const __nv_bfloat16* __restrict__ Wh,         // [4H][H] hi
    const __nv_bfloat16* __restrict__ Wl,         // [4H][H] lo
    __nv_bfloat16* __restrict__ hh,               // [T][B][H] hi
    __nv_bfloat16* __restrict__ hl,               // [T][B][H] lo
    float* __restrict__ fout) {                   // optional [B][T][H] output
    extern __shared__ __align__(16) unsigned char smem[];
    __nv_bfloat16* sWh = (__nv_bfloat16*)smem;        // 32 x 1032
    __nv_bfloat16* sWl = sWh + 32 * 1032;
    __nv_bfloat16* sAh = sWl + 32 * 1032;             // 2 bufs x 64 x 136
    __nv_bfloat16* sAl = sAh + 2 * 64 * 136;
    float* sXW = (float*)(sAl + 2 * 64 * 136);        // [64][32]
    float* zs4 = (float*)sAh;                          // [4][64][32] aliases A bufs

    const int tid = threadIdx.x, lane = tid & 31, wid = tid >> 5;
    const int g = lane >> 2, tg = lane & 3;
    const int mh = wid >> 2, ks = wid & 3;            // mh 0..3, ks 0..3
    const int j0 = blockIdx.x * 8;

    const uint32_t sAhB = (uint32_t)__cvta_generic_to_shared(sAh);
    const uint32_t sAlB = (uint32_t)__cvta_generic_to_shared(sAl);
    const uint32_t sXWB = (uint32_t)__cvta_generic_to_shared(sXW);

    // Preload Wh slice: row r = gate*8 + jj -> n = gate*1024 + j0 + jj
    for (int e = tid; e < 32 * 128; e += 512) {
        int r = e >> 7, k8 = (e & 127) << 3;
        int n = ((r >> 3) << 10) + j0 + (r & 7);
        *(uint4*)(sWh + r * 1032 + k8) = *(const uint4*)(Wh + (size_t)n * NH + k8);
        *(uint4*)(sWl + r * 1032 + k8) = *(const uint4*)(Wl + (size_t)n * NH + k8);
    }
    __syncthreads();

    float c0 = 0.f;  // one cell-state element per thread (512 items)

    for (int t = 0; t < NT; t++) {
        // Prefetch xW(t) slice: 8KB, one cp16 per thread (contiguous 1MB slab)
        {
            int b = tid >> 3, rem = tid & 7;
            int gate = rem >> 1, half = rem & 1;
            const float* src = xW + ((size_t)t * NB + b) * NG + (gate << 10) + j0 + half * 4;
            uint32_t d = sXWB + (uint32_t)(b * 32 + gate * 8 + half * 4) * 4;
            cp16(d, src);
            cp_commit();
        }

        if (t > 0) {
            const __nv_bfloat16* hsh = hh + (size_t)(t - 1) * NB * NH;
            const __nv_bfloat16* hsl = hl + (size_t)(t - 1) * NB * NH;

            auto issue = [&](int q, int bi) {
                int k0 = q * 128;
#pragma unroll
                for (int i = 0; i < 2; i++) {
                    int e = tid + i * 512;
                    int r = e >> 4, u = e & 15;
                    size_t go = (size_t)r * NH + k0 + u * 8;
                    uint32_t so = (uint32_t)(bi * 64 * 136 + r * 136 + u * 8) * 2;
                    cp16(sAhB + so, hsh + go);
                    cp16(sAlB + so, hsl + go);
                }
                cp_commit();
            };

            float acc[4][4];
#pragma unroll
            for (int nt = 0; nt < 4; nt++)
#pragma unroll
                for (int q = 0; q < 4; q++) acc[nt][q] = 0.f;

            issue(0, 0);
            for (int q = 0; q < 8; q++) {
                if (q < 7) { issue(q + 1, (q + 1) & 1); cp_wait<1>(); }
                else       { cp_wait<0>(); }
                __syncthreads();

                const __nv_bfloat16* Ah = sAh + (q & 1) * 64 * 136;
                const __nv_bfloat16* Al = sAl + (q & 1) * 64 * 136;
                const int k0 = q * 128;
                const int rb = mh * 16;
#pragma unroll
                for (int kq = 0; kq < 2; kq++) {
                    const int kk = ks * 32 + kq * 16;
                    uint32_t ah[4], al[4], bh[4][2], bl[4][2];
                    ah[0] = *(const uint32_t*)(&Ah[(rb + g) * 136 + kk + tg * 2]);
                    ah[1] = *(const uint32_t*)(&Ah[(rb + g + 8) * 136 + kk + tg * 2]);
                    ah[2] = *(const uint32_t*)(&Ah[(rb + g) * 136 + kk + tg * 2 + 8]);
                    ah[3] = *(const uint32_t*)(&Ah[(rb + g + 8) * 136 + kk + tg * 2 + 8]);
                    al[0] = *(const uint32_t*)(&Al[(rb + g) * 136 + kk + tg * 2]);
                    al[1] = *(const uint32_t*)(&Al[(rb + g + 8) * 136 + kk + tg * 2]);
                    al[2] = *(const uint32_t*)(&Al[(rb + g) * 136 + kk + tg * 2 + 8]);
                    al[3] = *(const uint32_t*)(&Al[(rb + g + 8) * 136 + kk + tg * 2 + 8]);
#pragma unroll
                    for (int nt = 0; nt < 4; nt++) {
                        int r = nt * 8 + g;
                        bh[nt][0] = *(const uint32_t*)(&sWh[r * 1032 + k0 + kk + tg * 2]);
                        bh[nt][1] = *(const uint32_t*)(&sWh[r * 1032 + k0 + kk + tg * 2 + 8]);
                        bl[nt][0] = *(const uint32_t*)(&sWl[r * 1032 + k0 + kk + tg * 2]);
                        bl[nt][1] = *(const uint32_t*)(&sWl[r * 1032 + k0 + kk + tg * 2 + 8]);
                    }
#pragma unroll
                    for (int nt = 0; nt < 4; nt++) {
                        mma_bf16(acc[nt], ah, bh[nt]);
                        mma_bf16(acc[nt], ah, bl[nt]);
                        mma_bf16(acc[nt], al, bh[nt]);
                    }
                }
                __syncthreads();
            }

            // A buffers now dead -> write ks-partials into aliased zs4
            float* zbase = zs4 + ks * 2048;
            int row = mh * 16 + g;
#pragma unroll
            for (int nt = 0; nt < 4; nt++) {
                int col = nt * 8 + tg * 2;
                zbase[row * 32 + col]           = acc[nt][0];
                zbase[row * 32 + col + 1]       = acc[nt][1];
                zbase[(row + 8) * 32 + col]     = acc[nt][2];
                zbase[(row + 8) * 32 + col + 1] = acc[nt][3];
            }
            __syncthreads();
        } else {
            cp_wait<0>();
            __syncthreads();
        }

        // Cell update: 512 (b, jj) items, exactly one per thread
        {
            int b = tid >> 3, jj = tid & 7, j = j0 + jj;
            int bc = b * 32;
            float zi = sXW[bc + jj];
            float zf = sXW[bc + 8 + jj];
            float zg = sXW[bc + 16 + jj];
            float zo = sXW[bc + 24 + jj];
            if (t > 0) {
#pragma unroll
                for (int k2 = 0; k2 < 4; k2++) {
                    const float* zz = zs4 + k2 * 2048 + bc;
                    zi += zz[jj];
                    zf += zz[8 + jj];
                    zg += zz[16 + jj];
                    zo += zz[24 + jj];
                }
            }
            float iv = 1.f / (1.f + __expf(-zi));
            float fv = 1.f / (1.f + __expf(-zf));
            float gv = tanhf(zg);
            float ov = 1.f / (1.f + __expf(-zo));
            float cn = fv * c0 + iv * gv;
            c0 = cn;
            float hv = ov * tanhf(cn);
            size_t ho = ((size_t)t * NB + b) * NH + j;       // time-major
            __nv_bfloat16 hb = __float2bfloat16(hv);
            hh[ho] = hb;
            hl[ho] = __float2bfloat16(hv - __bfloat162float(hb));
            if (fout) fout[((size_t)b * NT + t) * NH + j] = hv;  // [B][T][H]
        }

        grid_sync();  // publish h(t) before any CTA reads it at t+1
    }
}

// ---------------------------------------------------------------------------
// kernel_launch: 6 graph nodes.
// split(0) -> nudge(1) -> gemm0(2) -> seq0(3 = ncu slot) -> gemm1(4) -> seq1(5)
// ---------------------------------------------------------------------------
extern "C" void kernel_launch(void* const* d_in, const int* in_sizes, int n_in,
                              void* d_out, int out_size) {
    (void)in_sizes; (void)n_in; (void)out_size;
    const float* x   = (const float*)d_in[0];
    const float* Wx0 = (const float*)d_in[1];
    const float* Wh0 = (const float*)d_in[2];
    const float* b0  = (const float*)d_in[3];
    const float* Wx1 = (const float*)d_in[4];
    const float* Wh1 = (const float*)d_in[5];
    const float* b1  = (const float*)d_in[6];
    float* out = (float*)d_out;

    float* xW;
    __nv_bfloat16 *xh, *xl, *hhp, *hlp;
    __nv_bfloat16 *wx0h, *wx0l, *wh0h, *wh0l, *wx1h, *wx1l, *wh1h, *wh1l;
    cudaGetSymbolAddress((void**)&xW, g_xW);
    cudaGetSymbolAddress((void**)&xh, g_xh);
    cudaGetSymbolAddress((void**)&xl, g_xl);
    cudaGetSymbolAddress((void**)&hhp, g_hh);
    cudaGetSymbolAddress((void**)&hlp, g_hl);
    cudaGetSymbolAddress((void**)&wx0h, g_Wx0h);
    cudaGetSymbolAddress((void**)&wx0l, g_Wx0l);
    cudaGetSymbolAddress((void**)&wh0h, g_Wh0h);
    cudaGetSymbolAddress((void**)&wh0l, g_Wh0l);
    cudaGetSymbolAddress((void**)&wx1h, g_Wx1h);
    cudaGetSymbolAddress((void**)&wx1l, g_Wx1l);
    cudaGetSymbolAddress((void**)&wh1h, g_Wh1h);
    cudaGetSymbolAddress((void**)&wh1l, g_Wh1l);

    cudaFuncSetAttribute(lstm_seq, cudaFuncAttributeMaxDynamicSharedMemorySize,
                         SEQ_SMEM);

    dim3 gg(NG / 64, NM / 128);  // (64, 256)

    split_all<<<(unsigned)(SPLIT_TOTAL / 256), 256>>>(
        x, Wx0, Wh0, Wx1, Wh1,
        xh, xl, wx0h, wx0l, wh0h, wh0l, wx1h, wx1l, wh1h, wh1l);

    nudge<<<1, 32>>>();

    gemm_in<<<gg, 256>>>(xh, xl, wx0h, wx0l, b0, xW, ND);
    lstm_seq<<<NCTA, 512, SEQ_SMEM>>>(xW, wh0h, wh0l, hhp, hlp, nullptr);

    gemm_in<<<gg, 256>>>(hhp, hlp, wx1h, wx1l, b1, xW, NH);
    lstm_seq<<<NCTA, 512, SEQ_SMEM>>>(xW, wh1h, wh1l, hhp, hlp, out);
}

// round 11
// speedup vs baseline: 1.1153x; 1.1153x over previous
#include <cuda_runtime.h>
#include <cuda_bf16.h>
#include <cstdint>
#include <math.h>

// Problem dims (fixed per reference setup_inputs)
#define NB 64
#define NT 512
#define ND 512
#define NH 1024
#define NG 4096
#define NM (NB * NT)
#define NCTA 128     // persistent grid: 128 CTAs (one per 8-column slice of H)

// ---------------------------------------------------------------------------
// Device scratch (allocation-free rule: __device__ globals)
// xW and h buffers are TIME-MAJOR: xW[t][b][4H], h[t][b][H].
// ---------------------------------------------------------------------------
__device__ float g_xW[(size_t)NM * NG];
__device__ __nv_bfloat16 g_xh[(size_t)NM * ND], g_xl[(size_t)NM * ND];   // x in [T][B][D]
__device__ __nv_bfloat16 g_hh[(size_t)NM * NH], g_hl[(size_t)NM * NH];   // h in [T][B][H]
// Pre-split, transposed weights: [N=4096][K] bf16 hi/lo
__device__ __nv_bfloat16 g_Wx0h[(size_t)NG * ND], g_Wx0l[(size_t)NG * ND];
__device__ __nv_bfloat16 g_Wh0h[(size_t)NG * NH], g_Wh0l[(size_t)NG * NH];
__device__ __nv_bfloat16 g_Wx1h[(size_t)NG * NH], g_Wx1l[(size_t)NG * NH];
__device__ __nv_bfloat16 g_Wh1h[(size_t)NG * NH], g_Wh1l[(size_t)NG * NH];
// Grid barrier state (zero-initialized; proven rounds 2/6/8/9)
__device__ unsigned g_barcnt = 0;
__device__ volatile unsigned g_bargen = 0;
__device__ float g_dummy;

// ---------------------------------------------------------------------------
// Helpers (NO tcgen05 — ptxas target is sm_100 plain)
// ---------------------------------------------------------------------------
__device__ __forceinline__ void cp16(uint32_t dst, const void* src) {
    asm volatile("cp.async.cg.shared.global [%0], [%1], 16;" :: "r"(dst), "l"(src));
}
__device__ __forceinline__ void cp_commit() {
    asm volatile("cp.async.commit_group;");
}
template <int N> __device__ __forceinline__ void cp_wait() {
    asm volatile("cp.async.wait_group %0;" :: "n"(N));
}

__device__ __forceinline__ void mma_bf16(float c[4], const uint32_t a[4],
                                         const uint32_t b[2]) {
    asm volatile(
        "mma.sync.aligned.m16n8k16.row.col.f32.bf16.bf16.f32 "
        "{%0,%1,%2,%3}, {%4,%5,%6,%7}, {%8,%9}, {%0,%1,%2,%3};"
        : "+f"(c[0]), "+f"(c[1]), "+f"(c[2]), "+f"(c[3])
        : "r"(a[0]), "r"(a[1]), "r"(a[2]), "r"(a[3]), "r"(b[0]), "r"(b[1]));
}

// Grid barrier — round-6 implementation (passed on hardware 4x). Bounded spin.
__device__ __forceinline__ void grid_sync() {
    __threadfence();
    __syncthreads();
    if (threadIdx.x == 0) {
        unsigned gen = g_bargen;
        if (atomicAdd(&g_barcnt, 1u) == NCTA - 1) {
            g_barcnt = 0;
            __threadfence();
            g_bargen = gen + 1;
        } else {
            for (long i = 0; i < 200000000L && g_bargen == gen; i++) { }
        }
    }
    __syncthreads();
    __threadfence();
}

// Tiny no-op node: keeps lstm_seq L0 at replay index 3 (the ncu capture slot).
__global__ void nudge() {
    if (threadIdx.x == 0) g_dummy = 1.0f;
}

// ---------------------------------------------------------------------------
// Fused split kernel. Region 0 also PERMUTES x from [B][T][D] to [T][B][D].
// ---------------------------------------------------------------------------
__global__ void split_all(
    const float* __restrict__ x,   const float* __restrict__ Wx0,
    const float* __restrict__ Wh0, const float* __restrict__ Wx1,
    const float* __restrict__ Wh1,
    __nv_bfloat16* __restrict__ xh,   __nv_bfloat16* __restrict__ xl,
    __nv_bfloat16* __restrict__ wx0h, __nv_bfloat16* __restrict__ wx0l,
    __nv_bfloat16* __restrict__ wh0h, __nv_bfloat16* __restrict__ wh0l,
    __nv_bfloat16* __restrict__ wx1h, __nv_bfloat16* __restrict__ wx1l,
    __nv_bfloat16* __restrict__ wh1h, __nv_bfloat16* __restrict__ wh1l) {
    const long R0 = (long)NM * ND;               // x
    const long R1 = R0 + (long)NG * ND;          // Wx0 (K=ND)
    const long R2 = R1 + (long)NG * NH;          // Wh0 (K=NH)
    const long R3 = R2 + (long)NG * NH;          // Wx1 (K=NH)
    long idx = (long)blockIdx.x * blockDim.x + threadIdx.x;

    float v;
    __nv_bfloat16 *hi, *lo;
    long o;
    if (idx < R0) {
        long b = idx / ((long)NT * ND);
        long rem = idx - b * ((long)NT * ND);
        long t = rem / ND, d = rem - t * ND;
        v = x[idx];
        o = (t * NB + b) * ND + d;               // time-major
        hi = xh; lo = xl;
    } else if (idx < R1) {
        o = idx - R0; long n = o / ND, k = o - n * ND;
        v = Wx0[k * NG + n]; hi = wx0h; lo = wx0l;
    } else if (idx < R2) {
        o = idx - R1; long n = o / NH, k = o - n * NH;
        v = Wh0[k * NG + n]; hi = wh0h; lo = wh0l;
    } else if (idx < R3) {
        o = idx - R2; long n = o / NH, k = o - n * NH;
        v = Wx1[k * NG + n]; hi = wx1h; lo = wx1l;
    } else {
        o = idx - R3; long n = o / NH, k = o - n * NH;
        v = Wh1[k * NG + n]; hi = wh1h; lo = wh1l;
    }
    __nv_bfloat16 h = __float2bfloat16(v);
    hi[o] = h;
    lo[o] = __float2bfloat16(v - __bfloat162float(h));
}
#define SPLIT_TOTAL ((long)NM * ND + (long)NG * ND + 3L * NG * NH)

// ---------------------------------------------------------------------------
// Input-projection GEMM (mma.sync, proven). Time-major row order m = t*NB+b.
// ---------------------------------------------------------------------------
__global__ __launch_bounds__(256) void gemm_in(
    const __nv_bfloat16* __restrict__ Ah, const __nv_bfloat16* __restrict__ Al,
    const __nv_bfloat16* __restrict__ Bh, const __nv_bfloat16* __restrict__ Bl,
    const float* __restrict__ bias, float* __restrict__ C, int K) {
    constexpr int BM = 128, BN = 64, BK = 32, AS = BK + 8;
    __shared__ __align__(16) __nv_bfloat16 sAh[BM * AS], sAl[BM * AS];
    __shared__ __align__(16) __nv_bfloat16 sBh[BN * AS], sBl[BN * AS];

    const int tid = threadIdx.x, lane = tid & 31, wid = tid >> 5;
    const int g = lane >> 2, tg = lane & 3;
    const int wm = wid & 3, wn = wid >> 2;
    const int m0 = blockIdx.y * BM, n0 = blockIdx.x * BN;

    float acc[2][4][4];
#pragma unroll
    for (int mt = 0; mt < 2; mt++)
#pragma unroll
        for (int nt = 0; nt < 4; nt++)
#pragma unroll
            for (int q = 0; q < 4; q++) acc[mt][nt][q] = 0.f;

    for (int k0 = 0; k0 < K; k0 += BK) {
#pragma unroll
        for (int i = 0; i < 2; i++) {
            int e = tid + i * 256;
            int r = e >> 2, k8 = (e & 3) << 3;
            *(uint4*)(sAh + r * AS + k8) =
                *(const uint4*)(Ah + (size_t)(m0 + r) * K + k0 + k8);
            *(uint4*)(sAl + r * AS + k8) =
                *(const uint4*)(Al + (size_t)(m0 + r) * K + k0 + k8);
        }
        {
            int r = tid >> 2, k8 = (tid & 3) << 3;
            *(uint4*)(sBh + r * AS + k8) =
                *(const uint4*)(Bh + (size_t)(n0 + r) * K + k0 + k8);
            *(uint4*)(sBl + r * AS + k8) =
                *(const uint4*)(Bl + (size_t)(n0 + r) * K + k0 + k8);
        }
        __syncthreads();

#pragma unroll
        for (int kk = 0; kk < BK; kk += 16) {
            uint32_t ah[2][4], al[2][4], bh[4][2], bl[4][2];
#pragma unroll
            for (int mt = 0; mt < 2; mt++) {
                int rb = wm * 32 + mt * 16;
                ah[mt][0] = *(const uint32_t*)(&sAh[(rb + g) * AS + kk + tg * 2]);
                ah[mt][1] = *(const uint32_t*)(&sAh[(rb + g + 8) * AS + kk + tg * 2]);
                ah[mt][2] = *(const uint32_t*)(&sAh[(rb + g) * AS + kk + tg * 2 + 8]);
                ah[mt][3] = *(const uint32_t*)(&sAh[(rb + g + 8) * AS + kk + tg * 2 + 8]);
                al[mt][0] = *(const uint32_t*)(&sAl[(rb + g) * AS + kk + tg * 2]);
                al[mt][1] = *(const uint32_t*)(&sAl[(rb + g + 8) * AS + kk + tg * 2]);
                al[mt][2] = *(const uint32_t*)(&sAl[(rb + g) * AS + kk + tg * 2 + 8]);
                al[mt][3] = *(const uint32_t*)(&sAl[(rb + g + 8) * AS + kk + tg * 2 + 8]);
            }
#pragma unroll
            for (int nt = 0; nt < 4; nt++) {
                int nb = wn * 32 + nt * 8 + g;
                bh[nt][0] = *(const uint32_t*)(&sBh[nb * AS + kk + tg * 2]);
                bh[nt][1] = *(const uint32_t*)(&sBh[nb * AS + kk + tg * 2 + 8]);
                bl[nt][0] = *(const uint32_t*)(&sBl[nb * AS + kk + tg * 2]);
                bl[nt][1] = *(const uint32_t*)(&sBl[nb * AS + kk + tg * 2 + 8]);
            }
#pragma unroll
            for (int mt = 0; mt < 2; mt++)
#pragma unroll
                for (int nt = 0; nt < 4; nt++) {
                    mma_bf16(acc[mt][nt], ah[mt], bh[nt]);
                    mma_bf16(acc[mt][nt], ah[mt], bl[nt]);
                    mma_bf16(acc[mt][nt], al[mt], bh[nt]);
                }
        }
        __syncthreads();
    }

#pragma unroll
    for (int mt = 0; mt < 2; mt++) {
        int row = m0 + wm * 32 + mt * 16 + g;
#pragma unroll
        for (int nt = 0; nt < 4; nt++) {
            int col = n0 + wn * 32 + nt * 8 + tg * 2;
            float b0v = bias[col], b1v = bias[col + 1];
            C[(size_t)row * NG + col]           = acc[mt][nt][0] + b0v;
            C[(size_t)row * NG + col + 1]       = acc[mt][nt][1] + b1v;
            C[(size_t)(row + 8) * NG + col]     = acc[mt][nt][2] + b0v;
            C[(size_t)(row + 8) * NG + col + 1] = acc[mt][nt][3] + b1v;
        }
    }
}

// ---------------------------------------------------------------------------
// Persistent recurrent kernel — WARP-PRIVATE PIPELINE.
// 128 CTAs x 512 threads (16 warps). Warp (mh=wid>>2, ks=wid&3) owns the
// DISJOINT A sub-tile rows[16mh,+16) x K[256ks,+256) and loads it itself:
// chunks of K=32, double-buffered in a per-warp SMEM region, synchronized by
// per-thread cp.async.wait_group + __syncwarp ONLY. Zero block barriers in
// the mainloop (was 16/step). Block-wide sync: 2 __syncthreads around the
// zs4 partial-sum exchange (zs4 aliases the then-dead A region) + grid_sync.
// ---------------------------------------------------------------------------
// SMEM: weights 2*32*1032*2 = 132096 | A staging 16 warps * 5120 = 81920
//       | sXW 8192  => 222208 B. zs4 (32KB) aliases A staging.
#define SEQ_SMEM (132096 + 81920 + 8192)

__global__ __launch_bounds__(512) void lstm_seq(
    const float* __restrict__ xW,                 // [T][B][4H]
    const __nv_bfloat16* __restrict__ Wh,         // [4H][H] hi
    const __nv_bfloat16* __restrict__ Wl,         // [4H][H] lo
    __nv_bfloat16* __restrict__ hh,               // [T][B][H] hi
    __nv_bfloat16* __restrict__ hl,               // [T][B][H] lo
    float* __restrict__ fout) {                   // optional [B][T][H] output
    extern __shared__ __align__(16) unsigned char smem[];
    __nv_bfloat16* sWh = (__nv_bfloat16*)smem;        // 32 x 1032
    __nv_bfloat16* sWl = sWh + 32 * 1032;
    __nv_bfloat16* sA  = sWl + 32 * 1032;             // 16 warps x [2][2][16][40]
    float* sXW = (float*)(sA + 40960);                // [64][32]
    float* zs4 = (float*)sA;                          // [4][64][32] aliases A

    const int tid = threadIdx.x, lane = tid & 31, wid = tid >> 5;
    const int g = lane >> 2, tg = lane & 3;
    const int mh = wid >> 2, ks = wid & 3;            // mh 0..3, ks 0..3
    const int j0 = blockIdx.x * 8;

    __nv_bfloat16* wbase = sA + wid * 2560;           // per-warp region (5120B)
    const uint32_t wb32 = (uint32_t)__cvta_generic_to_shared(wbase);
    const uint32_t sXWB = (uint32_t)__cvta_generic_to_shared(sXW);

    // Preload Wh slice: row r = gate*8 + jj -> n = gate*1024 + j0 + jj
    for (int e = tid; e < 32 * 128; e += 512) {
        int r = e >> 7, k8 = (e & 127) << 3;
        int n = ((r >> 3) << 10) + j0 + (r & 7);
        *(uint4*)(sWh + r * 1032 + k8) = *(const uint4*)(Wh + (size_t)n * NH + k8);
        *(uint4*)(sWl + r * 1032 + k8) = *(const uint4*)(Wl + (size_t)n * NH + k8);
    }
    __syncthreads();

    float c0 = 0.f;  // one cell-state element per thread (512 items)

    for (int t = 0; t < NT; t++) {
        // Prefetch xW(t) slice: 8KB, one cp16 per thread (oldest group)
        {
            int b = tid >> 3, rem = tid & 7;
            int gate = rem >> 1, half = rem & 1;
            const float* src = xW + ((size_t)t * NB + b) * NG + (gate << 10) + j0 + half * 4;
            uint32_t d = sXWB + (uint32_t)(b * 32 + gate * 8 + half * 4) * 4;
            cp16(d, src);
            cp_commit();
        }

        if (t > 0) {
            const __nv_bfloat16* hsh = hh + (size_t)(t - 1) * NB * NH;
            const __nv_bfloat16* hsl = hl + (size_t)(t - 1) * NB * NH;

            // Warp-private chunk load: 16 rows x 32 K-cols, hi+lo (4KB), 4 cp16/lane
            auto issue = [&](int q, int bi) {
                int kb = ks * 256 + q * 32;
#pragma unroll
                for (int i = 0; i < 2; i++) {
                    int slot = lane + i * 32;
                    int r = slot >> 2, u = slot & 3;
                    size_t go = (size_t)(mh * 16 + r) * NH + kb + u * 8;
                    uint32_t so = wb32 + (uint32_t)(bi * 1280 + r * 40 + u * 8) * 2;
                    cp16(so, hsh + go);
                    cp16(so + 1280, hsl + go);   // lo plane (+640 elems)
                }
                cp_commit();
            };

            float acc[4][4];
#pragma unroll
            for (int nt = 0; nt < 4; nt++)
#pragma unroll
                for (int q = 0; q < 4; q++) acc[nt][q] = 0.f;

            issue(0, 0);
            for (int q = 0; q < 8; q++) {
                if (q < 7) { issue(q + 1, (q + 1) & 1); cp_wait<1>(); }
                else       { cp_wait<0>(); }
                __syncwarp();

                const __nv_bfloat16* Ah = wbase + (q & 1) * 1280;
                const __nv_bfloat16* Al = Ah + 640;
                const int kb = ks * 256 + q * 32;
#pragma unroll
                for (int kq = 0; kq < 2; kq++) {
                    const int kk = kq * 16;
                    uint32_t ah[4], al[4], bh[4][2], bl[4][2];
                    ah[0] = *(const uint32_t*)(&Ah[g * 40 + kk + tg * 2]);
                    ah[1] = *(const uint32_t*)(&Ah[(g + 8) * 40 + kk + tg * 2]);
                    ah[2] = *(const uint32_t*)(&Ah[g * 40 + kk + tg * 2 + 8]);
                    ah[3] = *(const uint32_t*)(&Ah[(g + 8) * 40 + kk + tg * 2 + 8]);
                    al[0] = *(const uint32_t*)(&Al[g * 40 + kk + tg * 2]);
                    al[1] = *(const uint32_t*)(&Al[(g + 8) * 40 + kk + tg * 2]);
                    al[2] = *(const uint32_t*)(&Al[g * 40 + kk + tg * 2 + 8]);
                    al[3] = *(const uint32_t*)(&Al[(g + 8) * 40 + kk + tg * 2 + 8]);
                    const int kcol = kb + kk + tg * 2;
#pragma unroll
                    for (int nt = 0; nt < 4; nt++) {
                        int r = nt * 8 + g;
                        bh[nt][0] = *(const uint32_t*)(&sWh[r * 1032 + kcol]);
                        bh[nt][1] = *(const uint32_t*)(&sWh[r * 1032 + kcol + 8]);
                        bl[nt][0] = *(const uint32_t*)(&sWl[r * 1032 + kcol]);
                        bl[nt][1] = *(const uint32_t*)(&sWl[r * 1032 + kcol + 8]);
                    }
#pragma unroll
                    for (int nt = 0; nt < 4; nt++) {
                        mma_bf16(acc[nt], ah, bh[nt]);
                        mma_bf16(acc[nt], ah, bl[nt]);
                        mma_bf16(acc[nt], al, bh[nt]);
                    }
                }
            }

            __syncthreads();   // all warps done with A region -> zs4 may alias it

            float* zbase = zs4 + ks * 2048;
            int row = mh * 16 + g;
#pragma unroll
            for (int nt = 0; nt < 4; nt++) {
                int col = nt * 8 + tg * 2;
                zbase[row * 32 + col]           = acc[nt][0];
                zbase[row * 32 + col + 1]       = acc[nt][1];
                zbase[(row + 8) * 32 + col]     = acc[nt][2];
                zbase[(row + 8) * 32 + col + 1] = acc[nt][3];
            }
            __syncthreads();
        } else {
            cp_wait<0>();
            __syncthreads();
        }

        // Cell update: 512 (b, jj) items, exactly one per thread
        {
            int b = tid >> 3, jj = tid & 7, j = j0 + jj;
            int bc = b * 32;
            float zi = sXW[bc + jj];
            float zf = sXW[bc + 8 + jj];
            float zg = sXW[bc + 16 + jj];
            float zo = sXW[bc + 24 + jj];
            if (t > 0) {
#pragma unroll
                for (int k2 = 0; k2 < 4; k2++) {
                    const float* zz = zs4 + k2 * 2048 + bc;
                    zi += zz[jj];
                    zf += zz[8 + jj];
                    zg += zz[16 + jj];
                    zo += zz[24 + jj];
                }
            }
            float iv = 1.f / (1.f + __expf(-zi));
            float fv = 1.f / (1.f + __expf(-zf));
            float gv = tanhf(zg);
            float ov = 1.f / (1.f + __expf(-zo));
            float cn = fv * c0 + iv * gv;
            c0 = cn;
            float hv = ov * tanhf(cn);
            size_t ho = ((size_t)t * NB + b) * NH + j;       // time-major
            __nv_bfloat16 hb = __float2bfloat16(hv);
            hh[ho] = hb;
            hl[ho] = __float2bfloat16(hv - __bfloat162float(hb));
            if (fout) fout[((size_t)b * NT + t) * NH + j] = hv;  // [B][T][H]
        }

        grid_sync();  // publish h(t) before any CTA reads it at t+1
    }
}

// ---------------------------------------------------------------------------
// kernel_launch: 6 graph nodes.
// split(0) -> nudge(1) -> gemm0(2) -> seq0(3 = ncu slot) -> gemm1(4) -> seq1(5)
// ---------------------------------------------------------------------------
extern "C" void kernel_launch(void* const* d_in, const int* in_sizes, int n_in,
                              void* d_out, int out_size) {
    (void)in_sizes; (void)n_in; (void)out_size;
    const float* x   = (const float*)d_in[0];
    const float* Wx0 = (const float*)d_in[1];
    const float* Wh0 = (const float*)d_in[2];
    const float* b0  = (const float*)d_in[3];
    const float* Wx1 = (const float*)d_in[4];
    const float* Wh1 = (const float*)d_in[5];
    const float* b1  = (const float*)d_in[6];
    float* out = (float*)d_out;

    float* xW;
    __nv_bfloat16 *xh, *xl, *hhp, *hlp;
    __nv_bfloat16 *wx0h, *wx0l, *wh0h, *wh0l, *wx1h, *wx1l, *wh1h, *wh1l;
    cudaGetSymbolAddress((void**)&xW, g_xW);
    cudaGetSymbolAddress((void**)&xh, g_xh);
    cudaGetSymbolAddress((void**)&xl, g_xl);
    cudaGetSymbolAddress((void**)&hhp, g_hh);
    cudaGetSymbolAddress((void**)&hlp, g_hl);
    cudaGetSymbolAddress((void**)&wx0h, g_Wx0h);
    cudaGetSymbolAddress((void**)&wx0l, g_Wx0l);
    cudaGetSymbolAddress((void**)&wh0h, g_Wh0h);
    cudaGetSymbolAddress((void**)&wh0l, g_Wh0l);
    cudaGetSymbolAddress((void**)&wx1h, g_Wx1h);
    cudaGetSymbolAddress((void**)&wx1l, g_Wx1l);
    cudaGetSymbolAddress((void**)&wh1h, g_Wh1h);
    cudaGetSymbolAddress((void**)&wh1l, g_Wh1l);

    cudaFuncSetAttribute(lstm_seq, cudaFuncAttributeMaxDynamicSharedMemorySize,
                         SEQ_SMEM);

    dim3 gg(NG / 64, NM / 128);  // (64, 256)

    split_all<<<(unsigned)(SPLIT_TOTAL / 256), 256>>>(
        x, Wx0, Wh0, Wx1, Wh1,
        xh, xl, wx0h, wx0l, wh0h, wh0l, wx1h, wx1l, wh1h, wh1l);

    nudge<<<1, 32>>>();

    gemm_in<<<gg, 256>>>(xh, xl, wx0h, wx0l, b0, xW, ND);
    lstm_seq<<<NCTA, 512, SEQ_SMEM>>>(xW, wh0h, wh0l, hhp, hlp, nullptr);

    gemm_in<<<gg, 256>>>(hhp, hlp, wx1h, wx1l, b1, xW, NH);
    lstm_seq<<<NCTA, 512, SEQ_SMEM>>>(xW, wh1h, wh1l, hhp, hlp, out);
}